// round 2
// baseline (speedup 1.0000x reference)
#include <cuda_runtime.h>
#include <math.h>

#define NROWS 128
#define VOCAB 50257
#define HDIM  4096
#define LTOK  200

// ---------------- GEMM: C[N,V] = A[N,H] * B[V,H]^T (fp32) ----------------
#define BM 128
#define BN 128
#define BK 16
#define TM 8
#define TN 8
#define GT 256   // threads

__global__ __launch_bounds__(GT) void gemm_kernel(
    const float* __restrict__ A, const float* __restrict__ B, float* __restrict__ C)
{
    __shared__ float As[BK][BM];
    __shared__ float Bs[BK][BN];

    const int v0  = blockIdx.x * BN;
    const int tid = threadIdx.x;
    const int tx  = tid & 15;          // col group 0..15
    const int ty  = tid >> 4;          // row group 0..15
    const int row0 = ty * TM;
    const int col0 = tx * TN;

    float acc[TM][TN];
#pragma unroll
    for (int i = 0; i < TM; i++)
#pragma unroll
        for (int j = 0; j < TN; j++) acc[i][j] = 0.0f;

    for (int k0 = 0; k0 < HDIM; k0 += BK) {
        // Load A tile (128 x 16): 512 float4, 2 per thread
#pragma unroll
        for (int t = tid; t < BM * BK / 4; t += GT) {
            int m  = t / (BK / 4);
            int kq = (t % (BK / 4)) * 4;
            float4 a = *(const float4*)(A + (size_t)m * HDIM + k0 + kq);
            As[kq + 0][m] = a.x; As[kq + 1][m] = a.y;
            As[kq + 2][m] = a.z; As[kq + 3][m] = a.w;
        }
        // Load B tile (128 vocab rows x 16): guarded at the tail
#pragma unroll
        for (int t = tid; t < BN * BK / 4; t += GT) {
            int n  = t / (BK / 4);
            int kq = (t % (BK / 4)) * 4;
            int vr = v0 + n;
            float4 b = make_float4(0.f, 0.f, 0.f, 0.f);
            if (vr < VOCAB) b = *(const float4*)(B + (size_t)vr * HDIM + k0 + kq);
            Bs[kq + 0][n] = b.x; Bs[kq + 1][n] = b.y;
            Bs[kq + 2][n] = b.z; Bs[kq + 3][n] = b.w;
        }
        __syncthreads();

#pragma unroll
        for (int k = 0; k < BK; k++) {
            float ar[TM], br[TN];
            *(float4*)&ar[0] = *(const float4*)&As[k][row0];
            *(float4*)&ar[4] = *(const float4*)&As[k][row0 + 4];
            *(float4*)&br[0] = *(const float4*)&Bs[k][col0];
            *(float4*)&br[4] = *(const float4*)&Bs[k][col0 + 4];
#pragma unroll
            for (int i = 0; i < TM; i++)
#pragma unroll
                for (int j = 0; j < TN; j++)
                    acc[i][j] = fmaf(ar[i], br[j], acc[i][j]);
        }
        __syncthreads();
    }

#pragma unroll
    for (int i = 0; i < TM; i++) {
        int r = row0 + i;
#pragma unroll
        for (int j = 0; j < TN; j++) {
            int v = v0 + col0 + j;
            if (v < VOCAB) C[(size_t)r * VOCAB + v] = acc[i][j];
        }
    }
}

// ---------------- Penalties (rep / freq / presence), pre-temperature ----------------
__global__ void penalty_kernel(float* __restrict__ logits,
                               const int* __restrict__ out_tokens,
                               const float* __restrict__ pres,
                               const float* __restrict__ freq,
                               const float* __restrict__ rep)
{
    const int r = blockIdx.x;
    __shared__ int toks[LTOK];
    for (int i = threadIdx.x; i < LTOK; i += blockDim.x)
        toks[i] = out_tokens[r * LTOK + i];
    __syncthreads();

    const float rp = rep[r], fp = freq[r], pp = pres[r];
    for (int i = threadIdx.x; i < LTOK; i += blockDim.x) {
        int t = toks[i];
        int cnt = 0;
        bool first = true;
        for (int j = 0; j < LTOK; j++) {
            if (toks[j] == t) { cnt++; if (j < i) first = false; }
        }
        if (first) {
            float* p = logits + (size_t)r * VOCAB + t;
            float l = *p;
            l = (l > 0.0f) ? (l / rp) : (l * rp);
            l = l - fp * (float)cnt - pp;
            *p = l;
        }
    }
}

// ---------------- Per-row top-p/top-k + softmax (1 block = 1 row) ----------------
#define TPB 512
#define CAP 2048

__device__ __forceinline__ unsigned fmap(float x) {
    unsigned u = __float_as_uint(x);
    return (u & 0x80000000u) ? ~u : (u | 0x80000000u);  // monotone: larger float -> larger uint
}

__device__ __forceinline__ float warpMax(float v) {
#pragma unroll
    for (int o = 16; o; o >>= 1) v = fmaxf(v, __shfl_xor_sync(0xFFFFFFFFu, v, o));
    return v;
}
__device__ __forceinline__ float warpSum(float v) {
#pragma unroll
    for (int o = 16; o; o >>= 1) v += __shfl_xor_sync(0xFFFFFFFFu, v, o);
    return v;
}

__device__ float blockMax(float v, float* sh) {
    v = warpMax(v);
    int w = threadIdx.x >> 5, l = threadIdx.x & 31;
    if (l == 0) sh[w] = v;
    __syncthreads();
    if (w == 0) {
        float x = (l < (TPB >> 5)) ? sh[l] : -INFINITY;
        x = warpMax(x);
        if (l == 0) sh[0] = x;
    }
    __syncthreads();
    float r = sh[0];
    __syncthreads();
    return r;
}
__device__ float blockSum(float v, float* sh) {
    v = warpSum(v);
    int w = threadIdx.x >> 5, l = threadIdx.x & 31;
    if (l == 0) sh[w] = v;
    __syncthreads();
    if (w == 0) {
        float x = (l < (TPB >> 5)) ? sh[l] : 0.0f;
        x = warpSum(x);
        if (l == 0) sh[0] = x;
    }
    __syncthreads();
    float r = sh[0];
    __syncthreads();
    return r;
}

__global__ __launch_bounds__(TPB) void sample_kernel(
    float* __restrict__ logits,
    const float* __restrict__ temps,
    const float* __restrict__ top_ps,
    const int* __restrict__ top_ks)
{
    const int r   = blockIdx.x;
    const int tid = threadIdx.x;
    float* row = logits + (size_t)r * VOCAB;

    const float invT = 1.0f / temps[r];
    const float topp = top_ps[r];
    int topk = top_ks[r];
    if (topk < 1) topk = 1;
    if (topk > CAP - 1) topk = CAP - 1;   // dataset: topk <= 1023

    __shared__ float sred[32];
    __shared__ unsigned hist[256];
    __shared__ float cand[CAP];
    __shared__ float ps[CAP];
    __shared__ int cnt_sh;
    __shared__ unsigned sel_prefix;
    __shared__ int sel_k;
    __shared__ int m_sh;

    // Pass 1: row max of temperature-scaled logits
    float vmax = -INFINITY;
    for (int v = tid; v < VOCAB; v += TPB) vmax = fmaxf(vmax, row[v] * invT);
    const float m1 = blockMax(vmax, sred);

    // Pass 2: full-vocab softmax denominator
    float zs = 0.0f;
    for (int v = tid; v < VOCAB; v += TPB) zs += __expf(row[v] * invT - m1);
    const float Z = blockSum(zs, sred);
    const float invZ = 1.0f / Z;

    // Radix select: exact top_k-th largest value (mapped-uint domain, MSB first)
    unsigned prefix = 0;
    int kk = topk;
    for (int pass = 0; pass < 4; pass++) {
        const int shift = 24 - 8 * pass;
        for (int b = tid; b < 256; b += TPB) hist[b] = 0u;
        __syncthreads();
        if (pass == 0) {
            for (int v = tid; v < VOCAB; v += TPB) {
                unsigned u = fmap(row[v] * invT);
                atomicAdd(&hist[u >> 24], 1u);
            }
        } else {
            const unsigned hm = 0xFFFFFFFFu << (shift + 8);
            for (int v = tid; v < VOCAB; v += TPB) {
                unsigned u = fmap(row[v] * invT);
                if ((u & hm) == prefix) atomicAdd(&hist[(u >> shift) & 0xFFu], 1u);
            }
        }
        __syncthreads();
        if (tid == 0) {
            int cum = 0, b = 255;
            for (; b >= 0; b--) { cum += (int)hist[b]; if (cum >= kk) break; }
            if (b < 0) b = 0;
            sel_k = kk - (cum - (int)hist[b]);
            sel_prefix = prefix | ((unsigned)b << shift);
        }
        __syncthreads();
        prefix = sel_prefix;
        kk = sel_k;
        __syncthreads();
    }
    const unsigned t_u = prefix;

    // Gather candidates (>= top_k-th value) into shared
    if (tid == 0) cnt_sh = 0;
    __syncthreads();
    for (int v = tid; v < VOCAB; v += TPB) {
        float x = row[v] * invT;
        if (fmap(x) >= t_u) {
            int i = atomicAdd(&cnt_sh, 1);
            if (i < CAP) cand[i] = x;
        }
    }
    __syncthreads();
    const int ncand = min(cnt_sh, CAP);
    for (int i = tid; i < CAP; i += TPB)
        if (i >= ncand) cand[i] = -INFINITY;
    __syncthreads();

    // Bitonic sort descending (values only; stability irrelevant for equal values)
    for (int size = 2; size <= CAP; size <<= 1) {
        for (int stride = size >> 1; stride > 0; stride >>= 1) {
            for (int i = tid; i < CAP; i += TPB) {
                int j = i ^ stride;
                if (j > i) {
                    float a = cand[i], b = cand[j];
                    bool desc = ((i & size) == 0);
                    if (desc ? (a < b) : (a > b)) { cand[i] = b; cand[j] = a; }
                }
            }
            __syncthreads();
        }
    }

    // Inclusive prefix scan of sorted probabilities
    for (int i = tid; i < CAP; i += TPB) ps[i] = __expf(cand[i] - m1) * invZ;
    __syncthreads();
    for (int off = 1; off < CAP; off <<= 1) {
        float t0[CAP / TPB];
#pragma unroll
        for (int q = 0; q < CAP / TPB; q++) {
            int i = tid + q * TPB;
            t0[q] = (i >= off) ? ps[i - off] : 0.0f;
        }
        __syncthreads();
#pragma unroll
        for (int q = 0; q < CAP / TPB; q++) ps[tid + q * TPB] += t0[q];
        __syncthreads();
    }

    // m = #kept ranks: rank i kept iff i < topk and exclusive-prefix(i) <= topp.
    if (tid == 0) m_sh = 1;   // rank 0 always kept (prefix 0 <= topp, topk >= 1)
    __syncthreads();
    const int limit = min(topk, ncand);
#pragma unroll
    for (int q = 0; q < CAP / TPB; q++) {
        int i = tid + q * TPB;
        if (i > 0 && i < limit) {
            if (ps[i - 1] <= topp) atomicMax(&m_sh, i + 1);
        }
    }
    __syncthreads();
    const int m = m_sh;
    const float t_x = cand[m - 1];   // smallest kept scaled logit

    // Kept-set mass (exact, tie-inclusive)
    float zk = 0.0f;
    for (int v = tid; v < VOCAB; v += TPB) {
        float x = row[v] * invT;
        if (x >= t_x) zk += __expf(x - m1);
    }
    const float Zk = blockSum(zk, sred);
    const float invZk = 1.0f / Zk;

    // Final masked softmax, in place
    for (int v = tid; v < VOCAB; v += TPB) {
        float x = row[v] * invT;
        row[v] = (x >= t_x) ? __expf(x - m1) * invZk : 0.0f;
    }
}

// ---------------- launch ----------------
extern "C" void kernel_launch(void* const* d_in, const int* in_sizes, int n_in,
                              void* d_out, int out_size)
{
    const float* hidden = (const float*)d_in[0];   // [128,4096]
    const float* emb    = (const float*)d_in[1];   // [50257,4096]
    const int*   toks   = (const int*)  d_in[2];   // [128,200]
    const float* pres   = (const float*)d_in[3];
    const float* freq   = (const float*)d_in[4];
    const float* rep    = (const float*)d_in[5];
    const float* temps  = (const float*)d_in[6];
    const float* topps  = (const float*)d_in[7];
    const int*   topks  = (const int*)  d_in[8];
    float* out = (float*)d_out;                    // [128,50257] probs; used as logits scratch

    gemm_kernel<<<(VOCAB + BN - 1) / BN, GT>>>(hidden, emb, out);
    penalty_kernel<<<NROWS, 256>>>(out, toks, pres, freq, rep);
    sample_kernel<<<NROWS, TPB>>>(out, temps, topps, topks);
}

// round 6
// speedup vs baseline: 2.8294x; 2.8294x over previous
#include <cuda_runtime.h>
#include <cuda_bf16.h>
#include <math.h>
#include <stdint.h>

#define NROWS 128
#define VOCAB 50257
#define HDIM  4096
#define LTOK  200

// ==================== A pre-split (fp32 -> bf16 hi + bf16 lo) ====================

__device__ __nv_bfloat16 g_Ah[NROWS * HDIM];
__device__ __nv_bfloat16 g_Al[NROWS * HDIM];

__global__ void convert_a_kernel(const float* __restrict__ A) {
    int i = (blockIdx.x * blockDim.x + threadIdx.x) * 4;
    if (i >= NROWS * HDIM) return;
    float4 a = *(const float4*)(A + i);
    __nv_bfloat162 h01 = __floats2bfloat162_rn(a.x, a.y);
    __nv_bfloat162 h23 = __floats2bfloat162_rn(a.z, a.w);
    float r0 = a.x - __bfloat162float(h01.x);
    float r1 = a.y - __bfloat162float(h01.y);
    float r2 = a.z - __bfloat162float(h23.x);
    float r3 = a.w - __bfloat162float(h23.y);
    __nv_bfloat162 l01 = __floats2bfloat162_rn(r0, r1);
    __nv_bfloat162 l23 = __floats2bfloat162_rn(r2, r3);
    *(uint2*)(g_Ah + i) = make_uint2(*(uint32_t*)&h01, *(uint32_t*)&h23);
    *(uint2*)(g_Al + i) = make_uint2(*(uint32_t*)&l01, *(uint32_t*)&l23);
}

// ==================== HMMA GEMM: C[128,V] = A[128,H] * B[V,H]^T ====================
// CTA tile M=128 x N=128, K chunks of 64, double-buffered.
// 8 warps, each 64x32 (4 m-tiles x 4 n-tiles of m16n8k16).
// 3 MMA terms per tile: Ah*Bh + Al*Bh + Ah*Bl  (split bf16 ~ fp32 accuracy).

#define KC 64
#define NCHUNK (HDIM / KC)            // 64
#define SPITCH 72                     // bf16 elements per smem row (64 + 8 pad)
#define ARR_BYTES (128 * SPITCH * 2)  // 18432 per array
#define STAGE_BYTES (4 * ARR_BYTES)   // Ah, Al, Bh, Bl
#define GEMM_T 256
#define SMEM_DYN (2 * STAGE_BYTES)    // 147456

__device__ __forceinline__ uint32_t smem_u32(const void* p) {
    uint32_t a;
    asm("{ .reg .u64 t; cvta.to.shared.u64 t, %1; cvt.u32.u64 %0, t; }" : "=r"(a) : "l"(p));
    return a;
}
__device__ __forceinline__ void ldsm_x4(uint32_t* r, uint32_t addr) {
    asm volatile("ldmatrix.sync.aligned.m8n8.x4.shared.b16 {%0,%1,%2,%3}, [%4];"
                 : "=r"(r[0]), "=r"(r[1]), "=r"(r[2]), "=r"(r[3]) : "r"(addr));
}
__device__ __forceinline__ void mma_bf16(float* d, const uint32_t* a, uint32_t b0, uint32_t b1) {
    asm volatile("mma.sync.aligned.m16n8k16.row.col.f32.bf16.bf16.f32 "
                 "{%0,%1,%2,%3}, {%4,%5,%6,%7}, {%8,%9}, {%0,%1,%2,%3};"
                 : "+f"(d[0]), "+f"(d[1]), "+f"(d[2]), "+f"(d[3])
                 : "r"(a[0]), "r"(a[1]), "r"(a[2]), "r"(a[3]), "r"(b0), "r"(b1));
}
__device__ __forceinline__ void cp16(uint32_t dst, const void* src) {
    asm volatile("cp.async.cg.shared.global [%0], [%1], 16;" :: "r"(dst), "l"(src) : "memory");
}

extern __shared__ char dynsmem[];

__global__ __launch_bounds__(GEMM_T, 1) void gemm_hmma(
    const float* __restrict__ B, float* __restrict__ C)
{
    char* sm = dynsmem;
    const uint32_t sbase = smem_u32(sm);
    const int tid = threadIdx.x;
    const int l   = tid & 31;
    const int w   = tid >> 5;
    const int wm  = w & 1;            // 2 M blocks of 64
    const int wn  = w >> 1;           // 4 N blocks of 32
    const int v0  = blockIdx.x * 128;

    // lane-dependent ldmatrix offsets (in bf16 elements, relative to tile origin)
    const int a_off = (l & 15) * SPITCH + ((l >> 4) << 3);
    const int b_off = (((l >> 4) << 3) + (l & 7)) * SPITCH + (((l >> 3) & 1) << 3);

    float acc[4][4][4];
#pragma unroll
    for (int mt = 0; mt < 4; mt++)
#pragma unroll
        for (int nt = 0; nt < 4; nt++)
#pragma unroll
            for (int q = 0; q < 4; q++) acc[mt][nt][q] = 0.0f;

    float4 breg[8];

    auto ldg_b = [&](int c) {
#pragma unroll
        for (int i = 0; i < 8; i++) {
            int t = tid + i * GEMM_T;          // 0..2047
            int row = t >> 4, q = t & 15;
            int vr = v0 + row;
            float4 b = make_float4(0.f, 0.f, 0.f, 0.f);
            if (vr < VOCAB) b = *(const float4*)(B + (size_t)vr * HDIM + c * KC + q * 4);
            breg[i] = b;
        }
    };
    auto cpa_a = [&](int c, int s) {
        uint32_t dstA = sbase + s * STAGE_BYTES;
#pragma unroll
        for (int i = 0; i < 8; i++) {
            int t = tid + i * GEMM_T;          // 0..2047
            int arr = t >> 10;                 // 0=hi 1=lo
            int idx = t & 1023;
            int row = idx >> 3, q = idx & 7;
            const __nv_bfloat16* src = (arr ? g_Al : g_Ah) + row * HDIM + c * KC + q * 8;
            cp16(dstA + arr * ARR_BYTES + row * (SPITCH * 2) + q * 16, src);
        }
        asm volatile("cp.async.commit_group;" ::: "memory");
    };
    auto sts_b = [&](int s) {
        char* bh = sm + s * STAGE_BYTES + 2 * ARR_BYTES;
        char* bl = sm + s * STAGE_BYTES + 3 * ARR_BYTES;
#pragma unroll
        for (int i = 0; i < 8; i++) {
            int t = tid + i * GEMM_T;
            int row = t >> 4, q = t & 15;
            float4 b = breg[i];
            __nv_bfloat162 h01 = __floats2bfloat162_rn(b.x, b.y);
            __nv_bfloat162 h23 = __floats2bfloat162_rn(b.z, b.w);
            float r0 = b.x - __bfloat162float(h01.x);
            float r1 = b.y - __bfloat162float(h01.y);
            float r2 = b.z - __bfloat162float(h23.x);
            float r3 = b.w - __bfloat162float(h23.y);
            __nv_bfloat162 l01 = __floats2bfloat162_rn(r0, r1);
            __nv_bfloat162 l23 = __floats2bfloat162_rn(r2, r3);
            int off = row * (SPITCH * 2) + q * 8;
            *(uint2*)(bh + off) = make_uint2(*(uint32_t*)&h01, *(uint32_t*)&h23);
            *(uint2*)(bl + off) = make_uint2(*(uint32_t*)&l01, *(uint32_t*)&l23);
        }
    };

    // ---- preload chunk 0 ----
    ldg_b(0);
    cpa_a(0, 0);
    sts_b(0);
    asm volatile("cp.async.wait_group 0;" ::: "memory");
    __syncthreads();

    for (int c = 0; c < NCHUNK; ++c) {
        const int s = c & 1;
        if (c + 1 < NCHUNK) {
            ldg_b(c + 1);
            cpa_a(c + 1, s ^ 1);
        }

        // ---- compute chunk c from stage s ----
        const uint32_t stAh = sbase + s * STAGE_BYTES;
        const uint32_t stAl = stAh + ARR_BYTES;
        const uint32_t stBh = stAh + 2 * ARR_BYTES;
        const uint32_t stBl = stAh + 3 * ARR_BYTES;
        const int m0 = wm * 64;
        const int n0 = wn * 32;
#pragma unroll
        for (int ks = 0; ks < 4; ks++) {
            const int kk = ks * 16;
            uint32_t ah[4][4], al[4][4], bh[2][4], bl[2][4];
#pragma unroll
            for (int mt = 0; mt < 4; mt++) {
                int e = (m0 + mt * 16) * SPITCH + kk + a_off;
                ldsm_x4(ah[mt], stAh + e * 2);
                ldsm_x4(al[mt], stAl + e * 2);
            }
#pragma unroll
            for (int ntp = 0; ntp < 2; ntp++) {
                int e = (n0 + ntp * 16) * SPITCH + kk + b_off;
                ldsm_x4(bh[ntp], stBh + e * 2);
                ldsm_x4(bl[ntp], stBl + e * 2);
            }
#pragma unroll
            for (int mt = 0; mt < 4; mt++)
#pragma unroll
                for (int nt = 0; nt < 4; nt++) {
                    uint32_t b0h = bh[nt >> 1][(nt & 1) * 2], b1h = bh[nt >> 1][(nt & 1) * 2 + 1];
                    uint32_t b0l = bl[nt >> 1][(nt & 1) * 2], b1l = bl[nt >> 1][(nt & 1) * 2 + 1];
                    mma_bf16(acc[mt][nt], ah[mt], b0h, b1h);
                    mma_bf16(acc[mt][nt], al[mt], b0h, b1h);
                    mma_bf16(acc[mt][nt], ah[mt], b0l, b1l);
                }
        }
        __syncthreads();   // all warps done reading stage s before overwrite below

        if (c + 1 < NCHUNK) {
            sts_b(s ^ 1);
            asm volatile("cp.async.wait_group 0;" ::: "memory");
        }
        __syncthreads();
    }

    // ---- epilogue: fragments -> GMEM (scalar stores: VOCAB odd => odd rows
    //      make element index odd, so float2 would be misaligned) ----
    const int g = l >> 2, t4 = l & 3;
#pragma unroll
    for (int mt = 0; mt < 4; mt++) {
        int row = wm * 64 + mt * 16 + g;
#pragma unroll
        for (int nt = 0; nt < 4; nt++) {
            int col = v0 + wn * 32 + nt * 8 + t4 * 2;
            if (col < VOCAB) {
                float* p0 = C + (size_t)row * VOCAB + col;
                float* p1 = C + (size_t)(row + 8) * VOCAB + col;
                p0[0] = acc[mt][nt][0];
                p1[0] = acc[mt][nt][2];
                if (col + 1 < VOCAB) {
                    p0[1] = acc[mt][nt][1];
                    p1[1] = acc[mt][nt][3];
                }
            }
        }
    }
}

// ==================== Penalties ====================
__global__ void penalty_kernel(float* __restrict__ logits,
                               const int* __restrict__ out_tokens,
                               const float* __restrict__ pres,
                               const float* __restrict__ freq,
                               const float* __restrict__ rep)
{
    const int r = blockIdx.x;
    __shared__ int toks[LTOK];
    for (int i = threadIdx.x; i < LTOK; i += blockDim.x)
        toks[i] = out_tokens[r * LTOK + i];
    __syncthreads();

    const float rp = rep[r], fp = freq[r], pp = pres[r];
    for (int i = threadIdx.x; i < LTOK; i += blockDim.x) {
        int t = toks[i];
        int cnt = 0;
        bool first = true;
        for (int j = 0; j < LTOK; j++) {
            if (toks[j] == t) { cnt++; if (j < i) first = false; }
        }
        if (first) {
            float* p = logits + (size_t)r * VOCAB + t;
            float l = *p;
            l = (l > 0.0f) ? (l / rp) : (l * rp);
            l = l - fp * (float)cnt - pp;
            *p = l;
        }
    }
}

// ==================== Per-row top-p/top-k + softmax ====================
#define TPB 512
#define CAP 2048

__device__ __forceinline__ unsigned fmap(float x) {
    unsigned u = __float_as_uint(x);
    return (u & 0x80000000u) ? ~u : (u | 0x80000000u);
}
__device__ __forceinline__ float warpMax(float v) {
#pragma unroll
    for (int o = 16; o; o >>= 1) v = fmaxf(v, __shfl_xor_sync(0xFFFFFFFFu, v, o));
    return v;
}
__device__ __forceinline__ float warpSum(float v) {
#pragma unroll
    for (int o = 16; o; o >>= 1) v += __shfl_xor_sync(0xFFFFFFFFu, v, o);
    return v;
}
__device__ float blockMax(float v, float* sh) {
    v = warpMax(v);
    int w = threadIdx.x >> 5, l = threadIdx.x & 31;
    if (l == 0) sh[w] = v;
    __syncthreads();
    if (w == 0) {
        float x = (l < (TPB >> 5)) ? sh[l] : -INFINITY;
        x = warpMax(x);
        if (l == 0) sh[0] = x;
    }
    __syncthreads();
    float r = sh[0];
    __syncthreads();
    return r;
}
__device__ float blockSum(float v, float* sh) {
    v = warpSum(v);
    int w = threadIdx.x >> 5, l = threadIdx.x & 31;
    if (l == 0) sh[w] = v;
    __syncthreads();
    if (w == 0) {
        float x = (l < (TPB >> 5)) ? sh[l] : 0.0f;
        x = warpSum(x);
        if (l == 0) sh[0] = x;
    }
    __syncthreads();
    float r = sh[0];
    __syncthreads();
    return r;
}

__global__ __launch_bounds__(TPB) void sample_kernel(
    float* __restrict__ logits,
    const float* __restrict__ temps,
    const float* __restrict__ top_ps,
    const int* __restrict__ top_ks)
{
    const int r   = blockIdx.x;
    const int tid = threadIdx.x;
    float* row = logits + (size_t)r * VOCAB;

    const float invT = 1.0f / temps[r];
    const float topp = top_ps[r];
    int topk = top_ks[r];
    if (topk < 1) topk = 1;
    if (topk > CAP - 1) topk = CAP - 1;

    __shared__ float sred[32];
    __shared__ unsigned hist[256];
    __shared__ float cand[CAP];
    __shared__ float ps[CAP];
    __shared__ int cnt_sh;
    __shared__ unsigned sel_prefix;
    __shared__ int sel_k;
    __shared__ int m_sh;

    float vmax = -INFINITY;
    for (int v = tid; v < VOCAB; v += TPB) vmax = fmaxf(vmax, row[v] * invT);
    const float m1 = blockMax(vmax, sred);

    float zs = 0.0f;
    for (int v = tid; v < VOCAB; v += TPB) zs += __expf(row[v] * invT - m1);
    const float Z = blockSum(zs, sred);
    const float invZ = 1.0f / Z;

    unsigned prefix = 0;
    int kk = topk;
    for (int pass = 0; pass < 4; pass++) {
        const int shift = 24 - 8 * pass;
        for (int b = tid; b < 256; b += TPB) hist[b] = 0u;
        __syncthreads();
        if (pass == 0) {
            for (int v = tid; v < VOCAB; v += TPB) {
                unsigned u = fmap(row[v] * invT);
                atomicAdd(&hist[u >> 24], 1u);
            }
        } else {
            const unsigned hm = 0xFFFFFFFFu << (shift + 8);
            for (int v = tid; v < VOCAB; v += TPB) {
                unsigned u = fmap(row[v] * invT);
                if ((u & hm) == prefix) atomicAdd(&hist[(u >> shift) & 0xFFu], 1u);
            }
        }
        __syncthreads();
        if (tid == 0) {
            int cum = 0, b = 255;
            for (; b >= 0; b--) { cum += (int)hist[b]; if (cum >= kk) break; }
            if (b < 0) b = 0;
            sel_k = kk - (cum - (int)hist[b]);
            sel_prefix = prefix | ((unsigned)b << shift);
        }
        __syncthreads();
        prefix = sel_prefix;
        kk = sel_k;
        __syncthreads();
    }
    const unsigned t_u = prefix;

    if (tid == 0) cnt_sh = 0;
    __syncthreads();
    for (int v = tid; v < VOCAB; v += TPB) {
        float x = row[v] * invT;
        if (fmap(x) >= t_u) {
            int i = atomicAdd(&cnt_sh, 1);
            if (i < CAP) cand[i] = x;
        }
    }
    __syncthreads();
    const int ncand = min(cnt_sh, CAP);
    for (int i = tid; i < CAP; i += TPB)
        if (i >= ncand) cand[i] = -INFINITY;
    __syncthreads();

    for (int size = 2; size <= CAP; size <<= 1) {
        for (int stride = size >> 1; stride > 0; stride >>= 1) {
            for (int i = tid; i < CAP; i += TPB) {
                int j = i ^ stride;
                if (j > i) {
                    float a = cand[i], b = cand[j];
                    bool desc = ((i & size) == 0);
                    if (desc ? (a < b) : (a > b)) { cand[i] = b; cand[j] = a; }
                }
            }
            __syncthreads();
        }
    }

    for (int i = tid; i < CAP; i += TPB) ps[i] = __expf(cand[i] - m1) * invZ;
    __syncthreads();
    for (int off = 1; off < CAP; off <<= 1) {
        float t0[CAP / TPB];
#pragma unroll
        for (int q = 0; q < CAP / TPB; q++) {
            int i = tid + q * TPB;
            t0[q] = (i >= off) ? ps[i - off] : 0.0f;
        }
        __syncthreads();
#pragma unroll
        for (int q = 0; q < CAP / TPB; q++) ps[tid + q * TPB] += t0[q];
        __syncthreads();
    }

    if (tid == 0) m_sh = 1;
    __syncthreads();
    const int limit = min(topk, ncand);
#pragma unroll
    for (int q = 0; q < CAP / TPB; q++) {
        int i = tid + q * TPB;
        if (i > 0 && i < limit) {
            if (ps[i - 1] <= topp) atomicMax(&m_sh, i + 1);
        }
    }
    __syncthreads();
    const int m = m_sh;
    const float t_x = cand[m - 1];

    float zk = 0.0f;
    for (int v = tid; v < VOCAB; v += TPB) {
        float x = row[v] * invT;
        if (x >= t_x) zk += __expf(x - m1);
    }
    const float Zk = blockSum(zk, sred);
    const float invZk = 1.0f / Zk;

    for (int v = tid; v < VOCAB; v += TPB) {
        float x = row[v] * invT;
        row[v] = (x >= t_x) ? __expf(x - m1) * invZk : 0.0f;
    }
}

// ==================== launch ====================
extern "C" void kernel_launch(void* const* d_in, const int* in_sizes, int n_in,
                              void* d_out, int out_size)
{
    const float* hidden = (const float*)d_in[0];   // [128,4096]
    const float* emb    = (const float*)d_in[1];   // [50257,4096]
    const int*   toks   = (const int*)  d_in[2];   // [128,200]
    const float* pres   = (const float*)d_in[3];
    const float* freq   = (const float*)d_in[4];
    const float* rep    = (const float*)d_in[5];
    const float* temps  = (const float*)d_in[6];
    const float* topps  = (const float*)d_in[7];
    const int*   topks  = (const int*)  d_in[8];
    float* out = (float*)d_out;                    // [128,50257] probs; logits scratch

    cudaFuncSetAttribute(gemm_hmma, cudaFuncAttributeMaxDynamicSharedMemorySize, SMEM_DYN);

    convert_a_kernel<<<(NROWS * HDIM / 4 + 255) / 256, 256>>>(hidden);
    gemm_hmma<<<(VOCAB + 127) / 128, GEMM_T, SMEM_DYN>>>(emb, out);
    penalty_kernel<<<NROWS, 256>>>(out, toks, pres, freq, rep);
    sample_kernel<<<NROWS, TPB>>>(out, temps, topps, topks);
}

// round 7
// speedup vs baseline: 2.9882x; 1.0561x over previous
#include <cuda_runtime.h>
#include <cuda_bf16.h>
#include <math.h>
#include <stdint.h>

#define NROWS 128
#define VOCAB 50257
#define HDIM  4096
#define LTOK  200

// ==================== A pre-split (fp32 -> bf16 hi + bf16 lo) ====================

__device__ __nv_bfloat16 g_Ah[NROWS * HDIM];
__device__ __nv_bfloat16 g_Al[NROWS * HDIM];

__global__ void convert_a_kernel(const float* __restrict__ A) {
    int i = (blockIdx.x * blockDim.x + threadIdx.x) * 4;
    if (i >= NROWS * HDIM) return;
    float4 a = *(const float4*)(A + i);
    __nv_bfloat162 h01 = __floats2bfloat162_rn(a.x, a.y);
    __nv_bfloat162 h23 = __floats2bfloat162_rn(a.z, a.w);
    float r0 = a.x - __bfloat162float(h01.x);
    float r1 = a.y - __bfloat162float(h01.y);
    float r2 = a.z - __bfloat162float(h23.x);
    float r3 = a.w - __bfloat162float(h23.y);
    __nv_bfloat162 l01 = __floats2bfloat162_rn(r0, r1);
    __nv_bfloat162 l23 = __floats2bfloat162_rn(r2, r3);
    *(uint2*)(g_Ah + i) = make_uint2(*(uint32_t*)&h01, *(uint32_t*)&h23);
    *(uint2*)(g_Al + i) = make_uint2(*(uint32_t*)&l01, *(uint32_t*)&l23);
}

// ==================== HMMA GEMM: C[128,V] = A[128,H] * B[V,H]^T ====================
// CTA tile M=128 x N=128, K chunks of 64, double-buffered, 512 threads (16 warps).
// Each warp: 64x16 (4 m-tiles x 2 n-tiles of m16n8k16), 3 split-bf16 terms.

#define KC 64
#define NCHUNK (HDIM / KC)            // 64
#define SPITCH 72                     // bf16 elements per smem row (64 + 8 pad)
#define ARR_BYTES (128 * SPITCH * 2)  // 18432 per array
#define STAGE_BYTES (4 * ARR_BYTES)   // Ah, Al, Bh, Bl
#define GEMM_T 512
#define SMEM_DYN (2 * STAGE_BYTES)    // 147456

__device__ __forceinline__ uint32_t smem_u32(const void* p) {
    uint32_t a;
    asm("{ .reg .u64 t; cvta.to.shared.u64 t, %1; cvt.u32.u64 %0, t; }" : "=r"(a) : "l"(p));
    return a;
}
__device__ __forceinline__ void ldsm_x4(uint32_t* r, uint32_t addr) {
    asm volatile("ldmatrix.sync.aligned.m8n8.x4.shared.b16 {%0,%1,%2,%3}, [%4];"
                 : "=r"(r[0]), "=r"(r[1]), "=r"(r[2]), "=r"(r[3]) : "r"(addr));
}
__device__ __forceinline__ void mma_bf16(float* d, const uint32_t* a, uint32_t b0, uint32_t b1) {
    asm volatile("mma.sync.aligned.m16n8k16.row.col.f32.bf16.bf16.f32 "
                 "{%0,%1,%2,%3}, {%4,%5,%6,%7}, {%8,%9}, {%0,%1,%2,%3};"
                 : "+f"(d[0]), "+f"(d[1]), "+f"(d[2]), "+f"(d[3])
                 : "r"(a[0]), "r"(a[1]), "r"(a[2]), "r"(a[3]), "r"(b0), "r"(b1));
}
__device__ __forceinline__ void cp16(uint32_t dst, const void* src) {
    asm volatile("cp.async.cg.shared.global [%0], [%1], 16;" :: "r"(dst), "l"(src) : "memory");
}

extern __shared__ char dynsmem[];

__global__ __launch_bounds__(GEMM_T) void gemm_hmma(
    const float* __restrict__ B, float* __restrict__ C)
{
    char* sm = dynsmem;
    const uint32_t sbase = smem_u32(sm);
    const int tid = threadIdx.x;
    const int l   = tid & 31;
    const int w   = tid >> 5;         // 0..15
    const int wm  = w & 1;            // 2 M blocks of 64
    const int wn  = w >> 1;           // 8 N blocks of 16
    const int v0  = blockIdx.x * 128;

    const int a_off = (l & 15) * SPITCH + ((l >> 4) << 3);
    const int b_off = (((l >> 4) << 3) + (l & 7)) * SPITCH + (((l >> 3) & 1) << 3);

    float acc[4][2][4];
#pragma unroll
    for (int mt = 0; mt < 4; mt++)
#pragma unroll
        for (int nt = 0; nt < 2; nt++)
#pragma unroll
            for (int q = 0; q < 4; q++) acc[mt][nt][q] = 0.0f;

    float4 breg[4];

    auto ldg_b = [&](int c) {
#pragma unroll
        for (int i = 0; i < 4; i++) {
            int t = tid + i * GEMM_T;          // 0..2047
            int row = t >> 4, q = t & 15;
            int vr = v0 + row;
            float4 b = make_float4(0.f, 0.f, 0.f, 0.f);
            if (vr < VOCAB) b = *(const float4*)(B + (size_t)vr * HDIM + c * KC + q * 4);
            breg[i] = b;
        }
    };
    auto cpa_a = [&](int c, int s) {
        uint32_t dstA = sbase + s * STAGE_BYTES;
#pragma unroll
        for (int i = 0; i < 4; i++) {
            int t = tid + i * GEMM_T;          // 0..2047
            int arr = t >> 10;                 // 0=hi 1=lo
            int idx = t & 1023;
            int row = idx >> 3, q = idx & 7;
            const __nv_bfloat16* src = (arr ? g_Al : g_Ah) + row * HDIM + c * KC + q * 8;
            cp16(dstA + arr * ARR_BYTES + row * (SPITCH * 2) + q * 16, src);
        }
        asm volatile("cp.async.commit_group;" ::: "memory");
    };
    auto sts_b = [&](int s) {
        char* bh = sm + s * STAGE_BYTES + 2 * ARR_BYTES;
        char* bl = sm + s * STAGE_BYTES + 3 * ARR_BYTES;
#pragma unroll
        for (int i = 0; i < 4; i++) {
            int t = tid + i * GEMM_T;
            int row = t >> 4, q = t & 15;
            float4 b = breg[i];
            __nv_bfloat162 h01 = __floats2bfloat162_rn(b.x, b.y);
            __nv_bfloat162 h23 = __floats2bfloat162_rn(b.z, b.w);
            float r0 = b.x - __bfloat162float(h01.x);
            float r1 = b.y - __bfloat162float(h01.y);
            float r2 = b.z - __bfloat162float(h23.x);
            float r3 = b.w - __bfloat162float(h23.y);
            __nv_bfloat162 l01 = __floats2bfloat162_rn(r0, r1);
            __nv_bfloat162 l23 = __floats2bfloat162_rn(r2, r3);
            int off = row * (SPITCH * 2) + q * 8;
            *(uint2*)(bh + off) = make_uint2(*(uint32_t*)&h01, *(uint32_t*)&h23);
            *(uint2*)(bl + off) = make_uint2(*(uint32_t*)&l01, *(uint32_t*)&l23);
        }
    };

    // ---- preload chunk 0 ----
    ldg_b(0);
    cpa_a(0, 0);
    sts_b(0);
    asm volatile("cp.async.wait_group 0;" ::: "memory");
    __syncthreads();

    for (int c = 0; c < NCHUNK; ++c) {
        const int s = c & 1;
        if (c + 1 < NCHUNK) {
            ldg_b(c + 1);
            cpa_a(c + 1, s ^ 1);
        }

        const uint32_t stAh = sbase + s * STAGE_BYTES;
        const uint32_t stAl = stAh + ARR_BYTES;
        const uint32_t stBh = stAh + 2 * ARR_BYTES;
        const uint32_t stBl = stAh + 3 * ARR_BYTES;
        const int m0 = wm * 64;
        const int n0 = wn * 16;
#pragma unroll
        for (int ks = 0; ks < 4; ks++) {
            const int kk = ks * 16;
            uint32_t ah[4][4], al[4][4], bh[4], bl[4];
#pragma unroll
            for (int mt = 0; mt < 4; mt++) {
                int e = (m0 + mt * 16) * SPITCH + kk + a_off;
                ldsm_x4(ah[mt], stAh + e * 2);
                ldsm_x4(al[mt], stAl + e * 2);
            }
            {
                int e = n0 * SPITCH + kk + b_off;
                ldsm_x4(bh, stBh + e * 2);
                ldsm_x4(bl, stBl + e * 2);
            }
#pragma unroll
            for (int mt = 0; mt < 4; mt++)
#pragma unroll
                for (int nt = 0; nt < 2; nt++) {
                    uint32_t b0h = bh[nt * 2], b1h = bh[nt * 2 + 1];
                    uint32_t b0l = bl[nt * 2], b1l = bl[nt * 2 + 1];
                    mma_bf16(acc[mt][nt], ah[mt], b0h, b1h);
                    mma_bf16(acc[mt][nt], al[mt], b0h, b1h);
                    mma_bf16(acc[mt][nt], ah[mt], b0l, b1l);
                }
        }

        if (c + 1 < NCHUNK) {
            sts_b(s ^ 1);                      // safe: s^1 reads finished at prev barrier
            asm volatile("cp.async.wait_group 0;" ::: "memory");
        }
        __syncthreads();
    }

    // ---- epilogue: scalar stores (VOCAB odd -> odd rows break float2 alignment) ----
    const int g = l >> 2, t4 = l & 3;
#pragma unroll
    for (int mt = 0; mt < 4; mt++) {
        int row = wm * 64 + mt * 16 + g;
#pragma unroll
        for (int nt = 0; nt < 2; nt++) {
            int col = v0 + wn * 16 + nt * 8 + t4 * 2;
            if (col < VOCAB) {
                float* p0 = C + (size_t)row * VOCAB + col;
                float* p1 = C + (size_t)(row + 8) * VOCAB + col;
                p0[0] = acc[mt][nt][0];
                p1[0] = acc[mt][nt][2];
                if (col + 1 < VOCAB) {
                    p0[1] = acc[mt][nt][1];
                    p1[1] = acc[mt][nt][3];
                }
            }
        }
    }
}

// ==================== Penalties ====================
__global__ void penalty_kernel(float* __restrict__ logits,
                               const int* __restrict__ out_tokens,
                               const float* __restrict__ pres,
                               const float* __restrict__ freq,
                               const float* __restrict__ rep)
{
    const int r = blockIdx.x;
    __shared__ int toks[LTOK];
    for (int i = threadIdx.x; i < LTOK; i += blockDim.x)
        toks[i] = out_tokens[r * LTOK + i];
    __syncthreads();

    const float rp = rep[r], fp = freq[r], pp = pres[r];
    for (int i = threadIdx.x; i < LTOK; i += blockDim.x) {
        int t = toks[i];
        int cnt = 0;
        bool first = true;
        for (int j = 0; j < LTOK; j++) {
            if (toks[j] == t) { cnt++; if (j < i) first = false; }
        }
        if (first) {
            float* p = logits + (size_t)r * VOCAB + t;
            float l = *p;
            l = (l > 0.0f) ? (l / rp) : (l * rp);
            l = l - fp * (float)cnt - pp;
            *p = l;
        }
    }
}

// ==================== Per-row top-p/top-k + softmax ====================
// Fused passes: (max+hist0), (Z+hist1), gather@16-bit threshold (fallback: exact),
// then in-shared sort/scan; final = write-only zero-fill + sparse scatter.
#define TPB 512
#define CAP 2048

__device__ __forceinline__ unsigned fmap(float x) {
    unsigned u = __float_as_uint(x);
    return (u & 0x80000000u) ? ~u : (u | 0x80000000u);
}
__device__ __forceinline__ float warpMax(float v) {
#pragma unroll
    for (int o = 16; o; o >>= 1) v = fmaxf(v, __shfl_xor_sync(0xFFFFFFFFu, v, o));
    return v;
}
__device__ __forceinline__ float warpSum(float v) {
#pragma unroll
    for (int o = 16; o; o >>= 1) v += __shfl_xor_sync(0xFFFFFFFFu, v, o);
    return v;
}
__device__ float blockMax(float v, float* sh) {
    v = warpMax(v);
    int w = threadIdx.x >> 5, l = threadIdx.x & 31;
    if (l == 0) sh[w] = v;
    __syncthreads();
    if (w == 0) {
        float x = (l < (TPB >> 5)) ? sh[l] : -INFINITY;
        x = warpMax(x);
        if (l == 0) sh[0] = x;
    }
    __syncthreads();
    float r = sh[0];
    __syncthreads();
    return r;
}
__device__ float blockSum(float v, float* sh) {
    v = warpSum(v);
    int w = threadIdx.x >> 5, l = threadIdx.x & 31;
    if (l == 0) sh[w] = v;
    __syncthreads();
    if (w == 0) {
        float x = (l < (TPB >> 5)) ? sh[l] : 0.0f;
        x = warpSum(x);
        if (l == 0) sh[0] = x;
    }
    __syncthreads();
    float r = sh[0];
    __syncthreads();
    return r;
}

__global__ __launch_bounds__(TPB) void sample_kernel(
    float* __restrict__ logits,
    const float* __restrict__ temps,
    const float* __restrict__ top_ps,
    const int* __restrict__ top_ks)
{
    const int r   = blockIdx.x;
    const int tid = threadIdx.x;
    float* row = logits + (size_t)r * VOCAB;

    const float invT = 1.0f / temps[r];
    const float topp = top_ps[r];
    int topk = top_ks[r];
    if (topk < 1) topk = 1;
    if (topk > CAP - 1) topk = CAP - 1;

    __shared__ float sred[32];
    __shared__ unsigned hist[256];
    __shared__ float cand[CAP];
    __shared__ int   cidx[CAP];
    __shared__ float ps[CAP];
    __shared__ int cnt_sh;
    __shared__ unsigned s_T;       // gather threshold (domain of fmap>>s_SH)
    __shared__ int s_SH;
    __shared__ unsigned s_pref;    // running radix prefix
    __shared__ int s_kk;
    __shared__ int s_g;            // count strictly greater (across levels)
    __shared__ int s_need_fb;
    __shared__ int m_sh, j_sh;

    // row alignment: (r*VOCAB) mod 4 = r mod 4 (VOCAB%4==1)
    const int head = (4 - (r & 3)) & 3;
    const int nvec = (VOCAB - head) >> 2;
    const float4* vrow = (const float4*)(row + head);
    const int tbase = head + 4 * nvec;
    const int tcnt  = VOCAB - tbase;

    auto forall = [&](auto&& op) {
        if (tid < head) op(row[tid] * invT, tid);
        for (int i = tid; i < nvec; i += TPB) {
            float4 x4 = vrow[i];
            int v = head + 4 * i;
            op(x4.x * invT, v); op(x4.y * invT, v + 1);
            op(x4.z * invT, v + 2); op(x4.w * invT, v + 3);
        }
        if (tid < tcnt) op(row[tbase + tid] * invT, tbase + tid);
    };

    // ---- Pass A: row max + hist0 (top 8 bits) ----
    for (int b = tid; b < 256; b += TPB) hist[b] = 0u;
    __syncthreads();
    float vmax = -INFINITY;
    forall([&](float x, int v) {
        vmax = fmaxf(vmax, x);
        atomicAdd(&hist[fmap(x) >> 24], 1u);
    });
    const float m1 = blockMax(vmax, sred);   // internal syncs also fence hist

    if (tid == 0) {
        int cum = 0, b = 255;
        for (; b >= 0; b--) { cum += (int)hist[b]; if (cum >= topk) break; }
        if (b < 0) b = 0;
        s_g    = cum - (int)hist[b];
        s_kk   = topk - s_g;
        s_pref = (unsigned)b;
    }
    __syncthreads();
    const unsigned b0 = s_pref;
    __syncthreads();

    // ---- Pass B: Z + hist1 (bits [23:16] within bucket b0) ----
    for (int b = tid; b < 256; b += TPB) hist[b] = 0u;
    __syncthreads();
    float zs = 0.0f;
    forall([&](float x, int v) {
        unsigned u = fmap(x);
        zs += __expf(x - m1);
        if ((u >> 24) == b0) atomicAdd(&hist[(u >> 16) & 0xFFu], 1u);
    });
    const float Z = blockSum(zs, sred);
    const float invZ = 1.0f / Z;

    if (tid == 0) {
        int kk = s_kk, cum = 0, b = 255;
        for (; b >= 0; b--) { cum += (int)hist[b]; if (cum >= kk) break; }
        if (b < 0) b = 0;
        int g1 = cum - (int)hist[b];
        int total_ge = s_g + g1 + (int)hist[b];
        s_g   = s_g + g1;
        s_kk  = kk - g1;
        s_pref = (b0 << 8) | (unsigned)b;   // 16-bit prefix
        if (total_ge <= CAP) {
            s_T = s_pref; s_SH = 16; s_need_fb = 0;
        } else {
            s_need_fb = 1;
        }
    }
    __syncthreads();

    // ---- Rare fallback: refine to exact 32-bit threshold ----
    if (s_need_fb) {
        for (int pass = 2; pass < 4; pass++) {
            const int shift = 24 - 8 * pass;          // 8, then 0
            const unsigned pref = s_pref;
            for (int b = tid; b < 256; b += TPB) hist[b] = 0u;
            __syncthreads();
            forall([&](float x, int v) {
                unsigned u = fmap(x);
                if ((u >> (shift + 8)) == pref) atomicAdd(&hist[(u >> shift) & 0xFFu], 1u);
            });
            __syncthreads();
            if (tid == 0) {
                int kk = s_kk, cum = 0, b = 255;
                for (; b >= 0; b--) { cum += (int)hist[b]; if (cum >= kk) break; }
                if (b < 0) b = 0;
                s_kk = kk - (cum - (int)hist[b]);
                s_pref = (s_pref << 8) | (unsigned)b;
            }
            __syncthreads();
        }
        if (tid == 0) { s_T = s_pref; s_SH = 0; }
        __syncthreads();
    }
    const unsigned T = s_T;
    const int SH = s_SH;

    // ---- Gather (value, index) pairs ----
    if (tid == 0) cnt_sh = 0;
    __syncthreads();
    forall([&](float x, int v) {
        if ((fmap(x) >> SH) >= T) {
            int i = atomicAdd(&cnt_sh, 1);
            if (i < CAP) { cand[i] = x; cidx[i] = v; }
        }
    });
    __syncthreads();
    const int ncand = min(cnt_sh, CAP);
    for (int i = tid; i < CAP; i += TPB)
        if (i >= ncand) cand[i] = -INFINITY;
    __syncthreads();

    // ---- Bitonic sort desc (value, index pairs) ----
    for (int size = 2; size <= CAP; size <<= 1) {
        for (int stride = size >> 1; stride > 0; stride >>= 1) {
            for (int i = tid; i < CAP; i += TPB) {
                int j = i ^ stride;
                if (j > i) {
                    float a = cand[i], b = cand[j];
                    bool desc = ((i & size) == 0);
                    if (desc ? (a < b) : (a > b)) {
                        cand[i] = b; cand[j] = a;
                        int ta = cidx[i]; cidx[i] = cidx[j]; cidx[j] = ta;
                    }
                }
            }
            __syncthreads();
        }
    }

    // ---- Inclusive prefix scan of probs (full-softmax normalized) ----
    for (int i = tid; i < CAP; i += TPB) ps[i] = __expf(cand[i] - m1) * invZ;
    __syncthreads();
    for (int off = 1; off < CAP; off <<= 1) {
        float t0[CAP / TPB];
#pragma unroll
        for (int q = 0; q < CAP / TPB; q++) {
            int i = tid + q * TPB;
            t0[q] = (i >= off) ? ps[i - off] : 0.0f;
        }
        __syncthreads();
#pragma unroll
        for (int q = 0; q < CAP / TPB; q++) ps[tid + q * TPB] += t0[q];
        __syncthreads();
    }

    // ---- kept count m: rank i kept iff i < topk and exclusive-prefix <= topp ----
    if (tid == 0) m_sh = 1;
    __syncthreads();
    const int limit = min(topk, ncand);
#pragma unroll
    for (int q = 0; q < CAP / TPB; q++) {
        int i = tid + q * TPB;
        if (i > 0 && i < limit) {
            if (ps[i - 1] <= topp) atomicMax(&m_sh, i + 1);
        }
    }
    __syncthreads();
    const int m = m_sh;
    const float t_x = cand[m - 1];

    // ---- Zk from scan (all x >= t_x are in cand): last j with cand[j] >= t_x ----
    if (tid == 0) j_sh = m - 1;
    __syncthreads();
    for (int i = tid; i < ncand; i += TPB)
        if (cand[i] >= t_x) atomicMax(&j_sh, i);
    __syncthreads();
    const float Zk = ps[j_sh] * Z;
    const float invZk = 1.0f / Zk;

    // ---- Write-only zero-fill, then sparse scatter of kept probs ----
    {
        float4 z4 = make_float4(0.f, 0.f, 0.f, 0.f);
        if (tid < head) row[tid] = 0.f;
        float4* wrow = (float4*)(row + head);
        for (int i = tid; i < nvec; i += TPB) wrow[i] = z4;
        if (tid < tcnt) row[tbase + tid] = 0.f;
    }
    __syncthreads();
    for (int i = tid; i < ncand; i += TPB) {
        if (cand[i] >= t_x) row[cidx[i]] = __expf(cand[i] - m1) * invZk;
    }
}

// ==================== launch ====================
extern "C" void kernel_launch(void* const* d_in, const int* in_sizes, int n_in,
                              void* d_out, int out_size)
{
    const float* hidden = (const float*)d_in[0];   // [128,4096]
    const float* emb    = (const float*)d_in[1];   // [50257,4096]
    const int*   toks   = (const int*)  d_in[2];   // [128,200]
    const float* pres   = (const float*)d_in[3];
    const float* freq   = (const float*)d_in[4];
    const float* rep    = (const float*)d_in[5];
    const float* temps  = (const float*)d_in[6];
    const float* topps  = (const float*)d_in[7];
    const int*   topks  = (const int*)  d_in[8];
    float* out = (float*)d_out;                    // [128,50257] probs; logits scratch

    cudaFuncSetAttribute(gemm_hmma, cudaFuncAttributeMaxDynamicSharedMemorySize, SMEM_DYN);

    convert_a_kernel<<<(NROWS * HDIM / 4 + 255) / 256, 256>>>(hidden);
    gemm_hmma<<<(VOCAB + 127) / 128, GEMM_T, SMEM_DYN>>>(emb, out);
    penalty_kernel<<<NROWS, 256>>>(out, toks, pres, freq, rep);
    sample_kernel<<<NROWS, TPB>>>(out, temps, topps, topks);
}

// round 8
// speedup vs baseline: 3.1462x; 1.0529x over previous
#include <cuda_runtime.h>
#include <cuda_bf16.h>
#include <math.h>
#include <stdint.h>

#define NROWS 128
#define VOCAB 50257
#define HDIM  4096
#define LTOK  200

// ==================== A pre-split (fp32 -> bf16 hi + bf16 lo) ====================

__device__ __nv_bfloat16 g_Ah[NROWS * HDIM];
__device__ __nv_bfloat16 g_Al[NROWS * HDIM];

__global__ void convert_a_kernel(const float* __restrict__ A) {
    int i = (blockIdx.x * blockDim.x + threadIdx.x) * 4;
    if (i >= NROWS * HDIM) return;
    float4 a = *(const float4*)(A + i);
    __nv_bfloat162 h01 = __floats2bfloat162_rn(a.x, a.y);
    __nv_bfloat162 h23 = __floats2bfloat162_rn(a.z, a.w);
    float r0 = a.x - __bfloat162float(h01.x);
    float r1 = a.y - __bfloat162float(h01.y);
    float r2 = a.z - __bfloat162float(h23.x);
    float r3 = a.w - __bfloat162float(h23.y);
    __nv_bfloat162 l01 = __floats2bfloat162_rn(r0, r1);
    __nv_bfloat162 l23 = __floats2bfloat162_rn(r2, r3);
    *(uint2*)(g_Ah + i) = make_uint2(*(uint32_t*)&h01, *(uint32_t*)&h23);
    *(uint2*)(g_Al + i) = make_uint2(*(uint32_t*)&l01, *(uint32_t*)&l23);
}

// ==================== HMMA GEMM: C[128,V] = A[128,H] * B[V,H]^T ====================
// CTA tile M=128 x N=64, 256 threads, 2 CTAs/SM co-resident (latency hiding).
// 8 warps: wm=w&3 (32-row block), wn=w>>2 (32-col block); per-warp 32x32.
// 3 MMA terms: Ah*Bh + Al*Bh + Ah*Bl (split bf16 ~ fp32 accuracy).

#define KC 64
#define NCHUNK (HDIM / KC)            // 64
#define SPITCH 72                     // bf16 per smem row (64 + 8 pad)
#define A_BYTES (128 * SPITCH * 2)    // 18432
#define B_BYTES (64 * SPITCH * 2)     // 9216
#define STAGE_BYTES (2 * A_BYTES + 2 * B_BYTES)  // 55296
#define GEMM_T 256
#define NTILE 64
#define SMEM_DYN (2 * STAGE_BYTES)    // 110592

__device__ __forceinline__ uint32_t smem_u32(const void* p) {
    uint32_t a;
    asm("{ .reg .u64 t; cvta.to.shared.u64 t, %1; cvt.u32.u64 %0, t; }" : "=r"(a) : "l"(p));
    return a;
}
__device__ __forceinline__ void ldsm_x4(uint32_t* r, uint32_t addr) {
    asm volatile("ldmatrix.sync.aligned.m8n8.x4.shared.b16 {%0,%1,%2,%3}, [%4];"
                 : "=r"(r[0]), "=r"(r[1]), "=r"(r[2]), "=r"(r[3]) : "r"(addr));
}
__device__ __forceinline__ void mma_bf16(float* d, const uint32_t* a, uint32_t b0, uint32_t b1) {
    asm volatile("mma.sync.aligned.m16n8k16.row.col.f32.bf16.bf16.f32 "
                 "{%0,%1,%2,%3}, {%4,%5,%6,%7}, {%8,%9}, {%0,%1,%2,%3};"
                 : "+f"(d[0]), "+f"(d[1]), "+f"(d[2]), "+f"(d[3])
                 : "r"(a[0]), "r"(a[1]), "r"(a[2]), "r"(a[3]), "r"(b0), "r"(b1));
}
__device__ __forceinline__ void cp16(uint32_t dst, const void* src) {
    asm volatile("cp.async.cg.shared.global [%0], [%1], 16;" :: "r"(dst), "l"(src) : "memory");
}

extern __shared__ char dynsmem[];

__global__ __launch_bounds__(GEMM_T, 2) void gemm_hmma(
    const float* __restrict__ B, float* __restrict__ C)
{
    char* sm = dynsmem;
    const uint32_t sbase = smem_u32(sm);
    const int tid = threadIdx.x;
    const int l   = tid & 31;
    const int w   = tid >> 5;         // 0..7
    const int wm  = w & 3;            // 4 M blocks of 32
    const int wn  = w >> 2;           // 2 N blocks of 32
    const int v0  = blockIdx.x * NTILE;

    const int a_off = (l & 15) * SPITCH + ((l >> 4) << 3);
    const int b_off = (((l >> 4) << 3) + (l & 7)) * SPITCH + (((l >> 3) & 1) << 3);

    float acc[2][4][4];
#pragma unroll
    for (int mt = 0; mt < 2; mt++)
#pragma unroll
        for (int nt = 0; nt < 4; nt++)
#pragma unroll
            for (int q = 0; q < 4; q++) acc[mt][nt][q] = 0.0f;

    float4 breg[4];

    auto ldg_b = [&](int c) {
#pragma unroll
        for (int i = 0; i < 4; i++) {
            int t = tid + i * GEMM_T;          // 0..1023
            int row = t >> 4, q = t & 15;
            int vr = v0 + row;
            float4 b = make_float4(0.f, 0.f, 0.f, 0.f);
            if (vr < VOCAB) b = *(const float4*)(B + (size_t)vr * HDIM + c * KC + q * 4);
            breg[i] = b;
        }
    };
    auto cpa_a = [&](int c, int s) {
        uint32_t dstA = sbase + s * STAGE_BYTES;
#pragma unroll
        for (int i = 0; i < 8; i++) {
            int t = tid + i * GEMM_T;          // 0..2047
            int arr = t >> 10;                 // 0=hi 1=lo
            int idx = t & 1023;
            int row = idx >> 3, q = idx & 7;
            const __nv_bfloat16* src = (arr ? g_Al : g_Ah) + row * HDIM + c * KC + q * 8;
            cp16(dstA + arr * A_BYTES + row * (SPITCH * 2) + q * 16, src);
        }
        asm volatile("cp.async.commit_group;" ::: "memory");
    };
    auto sts_b = [&](int s) {
        char* bh = sm + s * STAGE_BYTES + 2 * A_BYTES;
        char* bl = bh + B_BYTES;
#pragma unroll
        for (int i = 0; i < 4; i++) {
            int t = tid + i * GEMM_T;
            int row = t >> 4, q = t & 15;
            float4 b = breg[i];
            __nv_bfloat162 h01 = __floats2bfloat162_rn(b.x, b.y);
            __nv_bfloat162 h23 = __floats2bfloat162_rn(b.z, b.w);
            float r0 = b.x - __bfloat162float(h01.x);
            float r1 = b.y - __bfloat162float(h01.y);
            float r2 = b.z - __bfloat162float(h23.x);
            float r3 = b.w - __bfloat162float(h23.y);
            __nv_bfloat162 l01 = __floats2bfloat162_rn(r0, r1);
            __nv_bfloat162 l23 = __floats2bfloat162_rn(r2, r3);
            int off = row * (SPITCH * 2) + q * 8;
            *(uint2*)(bh + off) = make_uint2(*(uint32_t*)&h01, *(uint32_t*)&h23);
            *(uint2*)(bl + off) = make_uint2(*(uint32_t*)&l01, *(uint32_t*)&l23);
        }
    };

    // ---- preload chunk 0 ----
    ldg_b(0);
    cpa_a(0, 0);
    sts_b(0);
    asm volatile("cp.async.wait_group 0;" ::: "memory");
    __syncthreads();

    for (int c = 0; c < NCHUNK; ++c) {
        const int s = c & 1;
        if (c + 1 < NCHUNK) {
            ldg_b(c + 1);
            cpa_a(c + 1, s ^ 1);
        }

        const uint32_t stAh = sbase + s * STAGE_BYTES;
        const uint32_t stAl = stAh + A_BYTES;
        const uint32_t stBh = stAh + 2 * A_BYTES;
        const uint32_t stBl = stBh + B_BYTES;
        const int m0 = wm * 32;
        const int n0 = wn * 32;
#pragma unroll
        for (int ks = 0; ks < 4; ks++) {
            const int kk = ks * 16;
            uint32_t ah[2][4], al[2][4], bh[2][4], bl[2][4];
#pragma unroll
            for (int mt = 0; mt < 2; mt++) {
                int e = (m0 + mt * 16) * SPITCH + kk + a_off;
                ldsm_x4(ah[mt], stAh + e * 2);
                ldsm_x4(al[mt], stAl + e * 2);
            }
#pragma unroll
            for (int ntp = 0; ntp < 2; ntp++) {
                int e = (n0 + ntp * 16) * SPITCH + kk + b_off;
                ldsm_x4(bh[ntp], stBh + e * 2);
                ldsm_x4(bl[ntp], stBl + e * 2);
            }
#pragma unroll
            for (int mt = 0; mt < 2; mt++)
#pragma unroll
                for (int nt = 0; nt < 4; nt++) {
                    int ntp = nt >> 1, j = nt & 1;
                    uint32_t b0h = bh[ntp][j * 2], b1h = bh[ntp][j * 2 + 1];
                    uint32_t b0l = bl[ntp][j * 2], b1l = bl[ntp][j * 2 + 1];
                    mma_bf16(acc[mt][nt], ah[mt], b0h, b1h);
                    mma_bf16(acc[mt][nt], al[mt], b0h, b1h);
                    mma_bf16(acc[mt][nt], ah[mt], b0l, b1l);
                }
        }

        if (c + 1 < NCHUNK) {
            sts_b(s ^ 1);                      // s^1 reads finished at prev barrier
            asm volatile("cp.async.wait_group 0;" ::: "memory");
        }
        __syncthreads();
    }

    // ---- epilogue: scalar stores (VOCAB odd -> float2 misaligns on odd rows) ----
    const int g = l >> 2, t4 = l & 3;
#pragma unroll
    for (int mt = 0; mt < 2; mt++) {
        int row = wm * 32 + mt * 16 + g;
#pragma unroll
        for (int nt = 0; nt < 4; nt++) {
            int col = v0 + wn * 32 + nt * 8 + t4 * 2;
            if (col < VOCAB) {
                float* p0 = C + (size_t)row * VOCAB + col;
                float* p1 = C + (size_t)(row + 8) * VOCAB + col;
                p0[0] = acc[mt][nt][0];
                p1[0] = acc[mt][nt][2];
                if (col + 1 < VOCAB) {
                    p0[1] = acc[mt][nt][1];
                    p1[1] = acc[mt][nt][3];
                }
            }
        }
    }
}

// ==================== Fused penalties + top-p/top-k + softmax (1 block = 1 row) ====================
#define TPB 512
#define CAP 2048

__device__ __forceinline__ unsigned fmap(float x) {
    unsigned u = __float_as_uint(x);
    return (u & 0x80000000u) ? ~u : (u | 0x80000000u);
}
__device__ __forceinline__ float warpMax(float v) {
#pragma unroll
    for (int o = 16; o; o >>= 1) v = fmaxf(v, __shfl_xor_sync(0xFFFFFFFFu, v, o));
    return v;
}
__device__ __forceinline__ float warpSum(float v) {
#pragma unroll
    for (int o = 16; o; o >>= 1) v += __shfl_xor_sync(0xFFFFFFFFu, v, o);
    return v;
}
__device__ float blockMax(float v, float* sh) {
    v = warpMax(v);
    int w = threadIdx.x >> 5, l = threadIdx.x & 31;
    if (l == 0) sh[w] = v;
    __syncthreads();
    if (w == 0) {
        float x = (l < (TPB >> 5)) ? sh[l] : -INFINITY;
        x = warpMax(x);
        if (l == 0) sh[0] = x;
    }
    __syncthreads();
    float r = sh[0];
    __syncthreads();
    return r;
}
__device__ float blockSum(float v, float* sh) {
    v = warpSum(v);
    int w = threadIdx.x >> 5, l = threadIdx.x & 31;
    if (l == 0) sh[w] = v;
    __syncthreads();
    if (w == 0) {
        float x = (l < (TPB >> 5)) ? sh[l] : 0.0f;
        x = warpSum(x);
        if (l == 0) sh[0] = x;
    }
    __syncthreads();
    float r = sh[0];
    __syncthreads();
    return r;
}

__global__ __launch_bounds__(TPB) void sample_kernel(
    float* __restrict__ logits,
    const int* __restrict__ out_tokens,
    const float* __restrict__ pres,
    const float* __restrict__ freq,
    const float* __restrict__ rep,
    const float* __restrict__ temps,
    const float* __restrict__ top_ps,
    const int* __restrict__ top_ks)
{
    const int r   = blockIdx.x;
    const int tid = threadIdx.x;
    float* row = logits + (size_t)r * VOCAB;

    // ---- fused penalties ----
    __shared__ int toksh[LTOK];
    for (int i = tid; i < LTOK; i += TPB) toksh[i] = out_tokens[r * LTOK + i];
    __syncthreads();
    {
        const float rp = rep[r], fp = freq[r], pp = pres[r];
        for (int i = tid; i < LTOK; i += TPB) {
            int t = toksh[i];
            int cnt = 0;
            bool first = true;
            for (int j = 0; j < LTOK; j++) {
                if (toksh[j] == t) { cnt++; if (j < i) first = false; }
            }
            if (first) {
                float lg = row[t];
                lg = (lg > 0.0f) ? (lg / rp) : (lg * rp);
                row[t] = lg - fp * (float)cnt - pp;
            }
        }
    }
    __syncthreads();

    const float invT = 1.0f / temps[r];
    const float topp = top_ps[r];
    int topk = top_ks[r];
    if (topk < 1) topk = 1;
    if (topk > CAP - 1) topk = CAP - 1;

    __shared__ float sred[32];
    __shared__ unsigned hist[256];
    __shared__ float cand[CAP];
    __shared__ int   cidx[CAP];
    __shared__ float ps[CAP];
    __shared__ int cnt_sh;
    __shared__ unsigned s_T;
    __shared__ int s_SH;
    __shared__ unsigned s_pref;
    __shared__ int s_kk;
    __shared__ int s_g;
    __shared__ int s_need_fb;
    __shared__ int m_sh, j_sh;

    const int head = (4 - (r & 3)) & 3;
    const int nvec = (VOCAB - head) >> 2;
    const float4* vrow = (const float4*)(row + head);
    const int tbase = head + 4 * nvec;
    const int tcnt  = VOCAB - tbase;

    auto forall = [&](auto&& op) {
        if (tid < head) op(row[tid] * invT, tid);
        for (int i = tid; i < nvec; i += TPB) {
            float4 x4 = vrow[i];
            int v = head + 4 * i;
            op(x4.x * invT, v); op(x4.y * invT, v + 1);
            op(x4.z * invT, v + 2); op(x4.w * invT, v + 3);
        }
        if (tid < tcnt) op(row[tbase + tid] * invT, tbase + tid);
    };

    // ---- Pass A: max + hist0 ----
    for (int b = tid; b < 256; b += TPB) hist[b] = 0u;
    __syncthreads();
    float vmax = -INFINITY;
    forall([&](float x, int v) {
        vmax = fmaxf(vmax, x);
        atomicAdd(&hist[fmap(x) >> 24], 1u);
    });
    const float m1 = blockMax(vmax, sred);

    if (tid == 0) {
        int cum = 0, b = 255;
        for (; b >= 0; b--) { cum += (int)hist[b]; if (cum >= topk) break; }
        if (b < 0) b = 0;
        s_g    = cum - (int)hist[b];
        s_kk   = topk - s_g;
        s_pref = (unsigned)b;
    }
    __syncthreads();
    const unsigned b0 = s_pref;
    __syncthreads();

    // ---- Pass B: Z + hist1 ----
    for (int b = tid; b < 256; b += TPB) hist[b] = 0u;
    __syncthreads();
    float zs = 0.0f;
    forall([&](float x, int v) {
        unsigned u = fmap(x);
        zs += __expf(x - m1);
        if ((u >> 24) == b0) atomicAdd(&hist[(u >> 16) & 0xFFu], 1u);
    });
    const float Z = blockSum(zs, sred);
    const float invZ = 1.0f / Z;

    if (tid == 0) {
        int kk = s_kk, cum = 0, b = 255;
        for (; b >= 0; b--) { cum += (int)hist[b]; if (cum >= kk) break; }
        if (b < 0) b = 0;
        int g1 = cum - (int)hist[b];
        int total_ge = s_g + g1 + (int)hist[b];
        s_g   = s_g + g1;
        s_kk  = kk - g1;
        s_pref = (b0 << 8) | (unsigned)b;
        if (total_ge <= CAP) { s_T = s_pref; s_SH = 16; s_need_fb = 0; }
        else s_need_fb = 1;
    }
    __syncthreads();

    if (s_need_fb) {
        for (int pass = 2; pass < 4; pass++) {
            const int shift = 24 - 8 * pass;
            const unsigned pref = s_pref;
            for (int b = tid; b < 256; b += TPB) hist[b] = 0u;
            __syncthreads();
            forall([&](float x, int v) {
                unsigned u = fmap(x);
                if ((u >> (shift + 8)) == pref) atomicAdd(&hist[(u >> shift) & 0xFFu], 1u);
            });
            __syncthreads();
            if (tid == 0) {
                int kk = s_kk, cum = 0, b = 255;
                for (; b >= 0; b--) { cum += (int)hist[b]; if (cum >= kk) break; }
                if (b < 0) b = 0;
                s_kk = kk - (cum - (int)hist[b]);
                s_pref = (s_pref << 8) | (unsigned)b;
            }
            __syncthreads();
        }
        if (tid == 0) { s_T = s_pref; s_SH = 0; }
        __syncthreads();
    }
    const unsigned T = s_T;
    const int SH = s_SH;

    // ---- Gather (value,index) ----
    if (tid == 0) cnt_sh = 0;
    __syncthreads();
    forall([&](float x, int v) {
        if ((fmap(x) >> SH) >= T) {
            int i = atomicAdd(&cnt_sh, 1);
            if (i < CAP) { cand[i] = x; cidx[i] = v; }
        }
    });
    __syncthreads();
    const int ncand = min(cnt_sh, CAP);
    for (int i = tid; i < CAP; i += TPB)
        if (i >= ncand) cand[i] = -INFINITY;
    __syncthreads();

    // ---- Bitonic sort desc ----
    for (int size = 2; size <= CAP; size <<= 1) {
        for (int stride = size >> 1; stride > 0; stride >>= 1) {
            for (int i = tid; i < CAP; i += TPB) {
                int j = i ^ stride;
                if (j > i) {
                    float a = cand[i], b = cand[j];
                    bool desc = ((i & size) == 0);
                    if (desc ? (a < b) : (a > b)) {
                        cand[i] = b; cand[j] = a;
                        int ta = cidx[i]; cidx[i] = cidx[j]; cidx[j] = ta;
                    }
                }
            }
            __syncthreads();
        }
    }

    // ---- Prefix scan of probs ----
    for (int i = tid; i < CAP; i += TPB) ps[i] = __expf(cand[i] - m1) * invZ;
    __syncthreads();
    for (int off = 1; off < CAP; off <<= 1) {
        float t0[CAP / TPB];
#pragma unroll
        for (int q = 0; q < CAP / TPB; q++) {
            int i = tid + q * TPB;
            t0[q] = (i >= off) ? ps[i - off] : 0.0f;
        }
        __syncthreads();
#pragma unroll
        for (int q = 0; q < CAP / TPB; q++) ps[tid + q * TPB] += t0[q];
        __syncthreads();
    }

    if (tid == 0) m_sh = 1;
    __syncthreads();
    const int limit = min(topk, ncand);
#pragma unroll
    for (int q = 0; q < CAP / TPB; q++) {
        int i = tid + q * TPB;
        if (i > 0 && i < limit) {
            if (ps[i - 1] <= topp) atomicMax(&m_sh, i + 1);
        }
    }
    __syncthreads();
    const int m = m_sh;
    const float t_x = cand[m - 1];

    if (tid == 0) j_sh = m - 1;
    __syncthreads();
    for (int i = tid; i < ncand; i += TPB)
        if (cand[i] >= t_x) atomicMax(&j_sh, i);
    __syncthreads();
    const float Zk = ps[j_sh] * Z;
    const float invZk = 1.0f / Zk;

    // ---- zero-fill + sparse scatter ----
    {
        float4 z4 = make_float4(0.f, 0.f, 0.f, 0.f);
        if (tid < head) row[tid] = 0.f;
        float4* wrow = (float4*)(row + head);
        for (int i = tid; i < nvec; i += TPB) wrow[i] = z4;
        if (tid < tcnt) row[tbase + tid] = 0.f;
    }
    __syncthreads();
    for (int i = tid; i < ncand; i += TPB) {
        if (cand[i] >= t_x) row[cidx[i]] = __expf(cand[i] - m1) * invZk;
    }
}

// ==================== launch ====================
extern "C" void kernel_launch(void* const* d_in, const int* in_sizes, int n_in,
                              void* d_out, int out_size)
{
    const float* hidden = (const float*)d_in[0];   // [128,4096]
    const float* emb    = (const float*)d_in[1];   // [50257,4096]
    const int*   toks   = (const int*)  d_in[2];   // [128,200]
    const float* pres   = (const float*)d_in[3];
    const float* freq   = (const float*)d_in[4];
    const float* rep    = (const float*)d_in[5];
    const float* temps  = (const float*)d_in[6];
    const float* topps  = (const float*)d_in[7];
    const int*   topks  = (const int*)  d_in[8];
    float* out = (float*)d_out;                    // [128,50257] probs; logits scratch

    cudaFuncSetAttribute(gemm_hmma, cudaFuncAttributeMaxDynamicSharedMemorySize, SMEM_DYN);

    convert_a_kernel<<<(NROWS * HDIM / 4 + 255) / 256, 256>>>(hidden);
    gemm_hmma<<<(VOCAB + NTILE - 1) / NTILE, GEMM_T, SMEM_DYN>>>(emb, out);
    sample_kernel<<<NROWS, TPB>>>(out, toks, pres, freq, rep, temps, topps, topks);
}